// round 15
// baseline (speedup 1.0000x reference)
#include <cuda_runtime.h>
#include <cuda_bf16.h>
#include <cstdint>
#include <cstddef>

#define QLEN 1024
#define MLEN 1024
#define KLEN 2048
#define BSZ  4
#define DM   1024
#define NH   16
#define DH   64

typedef unsigned long long ull;

// ---------------- scratch (device globals; allocation is forbidden) ----------------
__device__ float g_Q [(size_t)BSZ * NH * QLEN * DH];   // [b][n][i][d]
__device__ float g_K [(size_t)BSZ * NH * KLEN * DH];   // [b][n][j][d]
__device__ float g_V [(size_t)BSZ * NH * KLEN * DH];   // [b][n][j][d]
__device__ float g_RK[(size_t)NH * KLEN * DH];         // [n][jr][d]
__device__ float g_Y [(size_t)QLEN * BSZ * DM];        // w + attn_out (pre-LN)

// bf16 split operands
__device__ __nv_bfloat16 g_catH[(size_t)2 * QLEN * BSZ * DM];  // [mems;w] rows
__device__ __nv_bfloat16 g_catL[(size_t)2 * QLEN * BSZ * DM];
__device__ __nv_bfloat16 g_rH  [(size_t)KLEN * DM];
__device__ __nv_bfloat16 g_rL  [(size_t)KLEN * DM];
__device__ __nv_bfloat16 g_avH [(size_t)QLEN * BSZ * DM];      // attn out hi
__device__ __nv_bfloat16 g_avL [(size_t)QLEN * BSZ * DM];      // attn out lo
__device__ __nv_bfloat16 g_WtH [5][(size_t)DM * DM];   // transposed weights [n][k]
__device__ __nv_bfloat16 g_WtL [5][(size_t)DM * DM];

#define MODE_Q 0
#define MODE_K 1
#define MODE_V 2
#define MODE_R 3
#define MODE_O 4

// ---------------- PTX helpers ----------------
__device__ __forceinline__ uint32_t smem_u32(const void* p) {
    uint32_t a;
    asm("{ .reg .u64 t; cvta.to.shared.u64 t, %1; cvt.u32.u64 %0, t; }"
        : "=r"(a) : "l"(p));
    return a;
}
__device__ __forceinline__ void ldsm_x4(uint32_t* r, uint32_t addr) {
    asm volatile("ldmatrix.sync.aligned.m8n8.x4.shared.b16 {%0,%1,%2,%3}, [%4];"
                 : "=r"(r[0]), "=r"(r[1]), "=r"(r[2]), "=r"(r[3]) : "r"(addr));
}
__device__ __forceinline__ void mma16816(float* c, const uint32_t* a,
                                         uint32_t b0, uint32_t b1) {
    asm volatile(
        "mma.sync.aligned.m16n8k16.row.col.f32.bf16.bf16.f32 "
        "{%0,%1,%2,%3}, {%4,%5,%6,%7}, {%8,%9}, {%0,%1,%2,%3};"
        : "+f"(c[0]), "+f"(c[1]), "+f"(c[2]), "+f"(c[3])
        : "r"(a[0]), "r"(a[1]), "r"(a[2]), "r"(a[3]), "r"(b0), "r"(b1));
}
// f32x2 packed math (sm_100+ base feature, PTX 8.6)
__device__ __forceinline__ ull f2_add(ull a, ull b) {
    ull c; asm("add.rn.f32x2 %0, %1, %2;" : "=l"(c) : "l"(a), "l"(b)); return c;
}
__device__ __forceinline__ ull f2_mul(ull a, ull b) {
    ull c; asm("mul.rn.f32x2 %0, %1, %2;" : "=l"(c) : "l"(a), "l"(b)); return c;
}
__device__ __forceinline__ ull f2_fma(ull a, ull b, ull c) {
    ull d; asm("fma.rn.f32x2 %0, %1, %2, %3;" : "=l"(d) : "l"(a), "l"(b), "l"(c)); return d;
}
__device__ __forceinline__ ull f2_splat(float x) {
    ull r; asm("mov.b64 %0, {%1, %1};" : "=l"(r) : "f"(x)); return r;
}
__device__ __forceinline__ void f2_unpack(ull v, float& lo, float& hi) {
    asm("mov.b64 {%0, %1}, %2;" : "=f"(lo), "=f"(hi) : "l"(v));
}
__device__ __forceinline__ void lds_v2(ull& x, ull& y, uint32_t a) {
    asm volatile("ld.shared.v2.u64 {%0, %1}, [%2];" : "=l"(x), "=l"(y) : "r"(a));
}

// ---------------- fused prep: splits ----------------
__device__ __forceinline__ void split_one(const float* __restrict__ in,
                                          __nv_bfloat16* __restrict__ hi,
                                          __nv_bfloat16* __restrict__ lo, int i)
{
    float4 v = ((const float4*)in)[i];
    __nv_bfloat16 h0 = __float2bfloat16(v.x), h1 = __float2bfloat16(v.y);
    __nv_bfloat16 h2 = __float2bfloat16(v.z), h3 = __float2bfloat16(v.w);
    __nv_bfloat16 l0 = __float2bfloat16(v.x - __bfloat162float(h0));
    __nv_bfloat16 l1 = __float2bfloat16(v.y - __bfloat162float(h1));
    __nv_bfloat16 l2 = __float2bfloat16(v.z - __bfloat162float(h2));
    __nv_bfloat16 l3 = __float2bfloat16(v.w - __bfloat162float(h3));
    ((__nv_bfloat162*)hi)[2 * i]     = __halves2bfloat162(h0, h1);
    ((__nv_bfloat162*)hi)[2 * i + 1] = __halves2bfloat162(h2, h3);
    ((__nv_bfloat162*)lo)[2 * i]     = __halves2bfloat162(l0, l1);
    ((__nv_bfloat162*)lo)[2 * i + 1] = __halves2bfloat162(l2, l3);
}

__global__ __launch_bounds__(256)
void prep_splits(const float* __restrict__ mems, const float* __restrict__ w,
                 const float* __restrict__ r)
{
    const int bx = blockIdx.x, t = threadIdx.x;
    if (bx < 4096) {
        split_one(mems, g_catH, g_catL, bx * 256 + t);
    } else if (bx < 8192) {
        split_one(w, g_catH + (size_t)4096 * DM, g_catL + (size_t)4096 * DM,
                  (bx - 4096) * 256 + t);
    } else {
        split_one(r, g_rH, g_rL, (bx - 8192) * 256 + t);
    }
}

__global__ __launch_bounds__(256)
void prep_wsplits(const float* __restrict__ Wq, const float* __restrict__ Wk,
                  const float* __restrict__ Wv, const float* __restrict__ Wr,
                  const float* __restrict__ Wo)
{
    __shared__ float tile[32][33];
    const int widx = blockIdx.x >> 10;
    const int loc  = blockIdx.x & 1023;
    const int n0 = (loc & 31) * 32, k0 = (loc >> 5) * 32;
    const int tx = threadIdx.x & 31, ty = threadIdx.x >> 5;
    const float* W = (widx == 0) ? Wq : (widx == 1) ? Wk
                   : (widx == 2) ? Wv : (widx == 3) ? Wr : Wo;
    __nv_bfloat16* hi = g_WtH[widx];
    __nv_bfloat16* lo = g_WtL[widx];
    for (int rr = ty; rr < 32; rr += 8)
        tile[rr][tx] = W[(size_t)(k0 + rr) * DM + n0 + tx];
    __syncthreads();
    for (int rr = ty; rr < 32; rr += 8) {
        float v = tile[tx][rr];
        __nv_bfloat16 h = __float2bfloat16(v);
        __nv_bfloat16 l = __float2bfloat16(v - __bfloat162float(h));
        hi[(size_t)(n0 + rr) * DM + k0 + tx] = h;
        lo[(size_t)(n0 + rr) * DM + k0 + tx] = l;
    }
}

// ---------------- mma.sync split-bf16 GEMM body ----------------
#define KSC  64
#define STR  72
#define MAT_BF (128 * STR)
#define GEMM_SMEM_BYTES (4 * MAT_BF * 2)

__device__ __forceinline__ void tgemm_body(
    int mode, int m0, int n0,
    const __nv_bfloat16* __restrict__ AH, const __nv_bfloat16* __restrict__ AL,
    const __nv_bfloat16* __restrict__ BH, const __nv_bfloat16* __restrict__ BL,
    const float* __restrict__ bias, const float* __restrict__ addend,
    __nv_bfloat16* smb)
{
    __nv_bfloat16* sAH = smb;
    __nv_bfloat16* sAL = smb + MAT_BF;
    __nv_bfloat16* sBH = smb + 2 * MAT_BF;
    __nv_bfloat16* sBL = smb + 3 * MAT_BF;

    const int t    = threadIdx.x;
    const int wid  = t >> 5;
    const int lane = t & 31;
    const int wm   = wid >> 2;
    const int wn   = wid & 3;

    const uint32_t sAHu = smem_u32(sAH), sALu = smem_u32(sAL);
    const uint32_t sBHu = smem_u32(sBH), sBLu = smem_u32(sBL);

    const int aoff  = (lane & 15) * STR + ((lane >> 4) << 3);
    const int b4off = lane * STR;

    float acc[4][4][4];
#pragma unroll
    for (int i = 0; i < 4; i++)
#pragma unroll
        for (int j = 0; j < 4; j++)
#pragma unroll
            for (int k = 0; k < 4; k++) acc[i][j][k] = 0.f;

    for (int c = 0; c < 16; c++) {
        __syncthreads();
        const size_t coff = (size_t)c * KSC;
#pragma unroll
        for (int i = 0; i < 4; i++) {
            const int idx = t + i * 256;
            const int row = idx >> 3, g = (idx & 7) * 8;
            *(uint4*)(sAH + row * STR + g) = *(const uint4*)(AH + (size_t)(m0 + row) * DM + coff + g);
            *(uint4*)(sAL + row * STR + g) = *(const uint4*)(AL + (size_t)(m0 + row) * DM + coff + g);
            *(uint4*)(sBH + row * STR + g) = *(const uint4*)(BH + (size_t)(n0 + row) * DM + coff + g);
            *(uint4*)(sBL + row * STR + g) = *(const uint4*)(BL + (size_t)(n0 + row) * DM + coff + g);
        }
        __syncthreads();

#pragma unroll
        for (int ks = 0; ks < KSC; ks += 16) {
            uint32_t bh0[4], bh8[4], bl0[4], bl8[4];
            const uint32_t bbase = (uint32_t)((wn * 32) * STR + ks + b4off) * 2;
            ldsm_x4(bh0, sBHu + bbase);
            ldsm_x4(bh8, sBHu + bbase + 16);
            ldsm_x4(bl0, sBLu + bbase);
            ldsm_x4(bl8, sBLu + bbase + 16);
#pragma unroll
            for (int mt = 0; mt < 4; mt++) {
                const int mrow = wm * 64 + mt * 16;
                uint32_t ah[4], al[4];
                ldsm_x4(ah, sAHu + (uint32_t)(mrow * STR + ks + aoff) * 2);
                ldsm_x4(al, sALu + (uint32_t)(mrow * STR + ks + aoff) * 2);
#pragma unroll
                for (int nt = 0; nt < 4; nt++) {
                    mma16816(acc[mt][nt], ah, bh0[nt], bh8[nt]);
                    mma16816(acc[mt][nt], ah, bl0[nt], bl8[nt]);
                    mma16816(acc[mt][nt], al, bh0[nt], bh8[nt]);
                }
            }
        }
    }

    const int g  = lane >> 2;
    const int cp = (lane & 3) * 2;
#pragma unroll
    for (int mt = 0; mt < 4; mt++) {
        const int rbase = m0 + wm * 64 + mt * 16;
#pragma unroll
        for (int nt = 0; nt < 4; nt++) {
            const int col = n0 + wn * 32 + nt * 8 + cp;
            const float b0 = bias[col], b1 = bias[col + 1];
            const int nn = col >> 6, d = col & 63;
#pragma unroll
            for (int hrow = 0; hrow < 2; hrow++) {
                const int row = rbase + g + hrow * 8;
                float v0 = acc[mt][nt][hrow * 2 + 0] + b0;
                float v1 = acc[mt][nt][hrow * 2 + 1] + b1;
                if (mode == MODE_O) {
                    const float2 ad = *(const float2*)(addend + (size_t)row * DM + col);
                    *(float2*)(g_Y + (size_t)row * DM + col) =
                        make_float2(v0 + ad.x, v1 + ad.y);
                } else if (mode == MODE_R) {
                    *(float2*)(g_RK + ((size_t)nn * KLEN + row) * DH + d) =
                        make_float2(v0, v1);
                } else if (mode == MODE_Q) {
                    const int ip = row >> 2, bb = row & 3;
                    *(float2*)(g_Q + (((size_t)bb * NH + nn) * QLEN + ip) * DH + d) =
                        make_float2(v0, v1);
                } else {
                    const int ip = row >> 2, bb = row & 3;
                    float* dst = (mode == MODE_K) ? g_K : g_V;
                    *(float2*)(dst + (((size_t)bb * NH + nn) * KLEN + ip) * DH + d) =
                        make_float2(v0, v1);
                }
            }
        }
    }
}

__global__ __launch_bounds__(256, 2)
void tgemm_qkvr(const float* __restrict__ bq, const float* __restrict__ bk,
                const float* __restrict__ bv, const float* __restrict__ br)
{
    extern __shared__ __align__(16) __nv_bfloat16 smb[];
    const int my = blockIdx.y;
    int mode, mt;
    const __nv_bfloat16 *AH, *AL;
    const float* bias;
    if (my < 32)        { mode = MODE_Q; mt = my;       AH = g_catH + (size_t)4096 * DM; AL = g_catL + (size_t)4096 * DM; bias = bq; }
    else if (my < 96)   { mode = MODE_K; mt = my - 32;  AH = g_catH; AL = g_catL; bias = bk; }
    else if (my < 160)  { mode = MODE_V; mt = my - 96;  AH = g_catH; AL = g_catL; bias = bv; }
    else                { mode = MODE_R; mt = my - 160; AH = g_rH;   AL = g_rL;   bias = br; }
    tgemm_body(mode, mt * 128, blockIdx.x * 128,
               AH, AL, g_WtH[mode], g_WtL[mode], bias, nullptr, smb);
}

__global__ __launch_bounds__(256, 2)
void tgemm_o(const float* __restrict__ bo, const float* __restrict__ w)
{
    extern __shared__ __align__(16) __nv_bfloat16 smb[];
    tgemm_body(MODE_O, blockIdx.y * 128, blockIdx.x * 128,
               g_avH, g_avL, g_WtH[4], g_WtL[4], bo, w, smb);
}

// ---------------- flash attention, f32x2-packed, natural [row][d] layout ----------------
// smem float offsets: qS 0, Ks 4096, Vs 8192, Rs 12288(128x64), Ps 20480(64x68),
//                     db 24832, BDc 24896 ; total 25024 floats = 100096 B
#define AOFF_QS 0
#define AOFF_KS 4096
#define AOFF_VS 8192
#define AOFF_RS 12288
#define AOFF_PS 20480
#define AOFF_DB 24832
#define AOFF_BDC 24896
#define ATTN_SMEM_FLOATS 25024
#define ATTN_SMEM_BYTES (ATTN_SMEM_FLOATS * 4)
#define PS_S 68

// swizzled float index: row stride 64, 16B-granule XOR swizzle, key=(row>>2)&15
__device__ __forceinline__ int swf(int row, int g) {
    return row * 64 + (((g ^ (row >> 2)) & 15) << 2);
}

__global__ __launch_bounds__(256, 2)
void attn_kernel(const float* __restrict__ rwb, const float* __restrict__ rrb)
{
    extern __shared__ float sm[];
    float* Ps  = sm + AOFF_PS;
    float* db  = sm + AOFF_DB;
    float* BDc = sm + AOFF_BDC;
    const uint32_t smu = smem_u32(sm);
    const uint32_t qSu = smu + AOFF_QS * 4;
    const uint32_t Ksu = smu + AOFF_KS * 4;
    const uint32_t Vsu = smu + AOFF_VS * 4;
    const uint32_t Rsu = smu + AOFF_RS * 4;

    const int t  = threadIdx.x;
    const int qt = 15 - (int)blockIdx.x;
    const int i0 = qt * 64;
    const int h  = blockIdx.y;
    const int b  = h >> 4;
    const int n  = h & 15;
    const int tx = t & 15;
    const int ty = t >> 4;

    const float* Qh = g_Q  + ((size_t)b * NH + n) * QLEN * DH;
    const float* Kh = g_K  + ((size_t)b * NH + n) * KLEN * DH;
    const float* Vh = g_V  + ((size_t)b * NH + n) * KLEN * DH;
    const float* Rh = g_RK + (size_t)n * KLEN * DH;

    if (t < 64) db[t] = rrb[n * DH + t] - rwb[n * DH + t];
    // q fill (includes + r_w_bias), natural layout + swizzle
    for (int e = t; e < 64 * 16; e += 256) {
        const int r = e >> 4, g = e & 15;
        float4 q4 = *(const float4*)(Qh + (size_t)(i0 + r) * DH + g * 4);
        float4 w4 = *(const float4*)(rwb + n * DH + g * 4);
        q4.x += w4.x; q4.y += w4.y; q4.z += w4.z; q4.w += w4.w;
        *(float4*)(sm + AOFF_QS + swf(r, g)) = q4;
    }

    const int dbase = tx * 4 - ty * 4 + 63;   // rk idx = dbase + j - i
    // per-thread precomputed bases
    uint32_t aq[4], ak[4], ar[7];
    int kr[7];
#pragma unroll
    for (int i = 0; i < 4; i++) aq[i] = qSu + (uint32_t)(ty * 4 + i) * 256;
#pragma unroll
    for (int j = 0; j < 4; j++) ak[j] = Ksu + (uint32_t)(tx * 4 + j) * 256;
#pragma unroll
    for (int o = 0; o < 7; o++) {
        const int ridx = dbase - 3 + o;
        ar[o] = Rsu + (uint32_t)ridx * 256;
        kr[o] = (ridx >> 2) & 15;
    }

    float m[4], l[4];
    ull acc2[4][2];
#pragma unroll
    for (int i = 0; i < 4; i++) {
        m[i] = -1e30f; l[i] = 0.f;
        acc2[i][0] = 0ull; acc2[i][1] = 0ull;
    }

    const int ntile = qt + 17;
    for (int jt = 0; jt < ntile; jt++) {
        const int j0 = jt * 64;
        __syncthreads();   // prior tile consumed (covers q fill on jt=0)

        for (int e = t; e < 64 * 16; e += 256) {
            const int c = e >> 4, g = e & 15;
            *(float4*)(sm + AOFF_KS + swf(c, g)) =
                *(const float4*)(Kh + (size_t)(j0 + c) * DH + g * 4);
            *(float4*)(sm + AOFF_VS + swf(c, g)) =
                *(const float4*)(Vh + (size_t)(j0 + c) * DH + g * 4);
        }
        const int rb = j0 - i0 + (QLEN - 64);
        for (int e = t; e < 128 * 16; e += 256) {
            const int ri = e & 127, g = e >> 7;
            const int jr = rb + ri;
            float4 r4 = make_float4(0.f, 0.f, 0.f, 0.f);
            if (jr < KLEN) r4 = *(const float4*)(Rh + (size_t)jr * DH + g * 4);
            *(float4*)(sm + AOFF_RS + swf(ri, g)) = r4;
        }
        __syncthreads();

        if (t < 128) {   // rank-1 BD term: BDc[t] = sum_d db[d]*R[t][d]
            float sum = 0.f;
#pragma unroll
            for (int g = 0; g < 16; g++) {
                float4 rv = *(const float4*)(sm + AOFF_RS + swf(t, g));
                float4 dv = *(const float4*)(db + g * 4);
                sum = fmaf(rv.x, dv.x, sum); sum = fmaf(rv.y, dv.y, sum);
                sum = fmaf(rv.z, dv.z, sum); sum = fmaf(rv.w, dv.w, sum);
            }
            BDc[t] = sum;
        }
        __syncthreads();

        // ---- score: s2[i][j] accumulates (even,odd) d-partials packed ----
        ull s2[4][4];
#pragma unroll
        for (int i = 0; i < 4; i++)
#pragma unroll
            for (int j = 0; j < 4; j++) s2[i][j] = 0ull;

#pragma unroll 1
        for (int g = 0; g < 16; g++) {
            ull qq0[4], qq1[4], kk0[4], kk1[4], rr0[7], rr1[7];
            const uint32_t oq = (uint32_t)((g ^ ty) << 4);
            const uint32_t ok = (uint32_t)((g ^ tx) << 4);
#pragma unroll
            for (int i = 0; i < 4; i++) lds_v2(qq0[i], qq1[i], aq[i] + oq);
#pragma unroll
            for (int j = 0; j < 4; j++) lds_v2(kk0[j], kk1[j], ak[j] + ok);
#pragma unroll
            for (int o = 0; o < 7; o++)
                lds_v2(rr0[o], rr1[o], ar[o] + (uint32_t)((g ^ kr[o]) << 4));
#pragma unroll
            for (int i = 0; i < 4; i++)
#pragma unroll
                for (int j = 0; j < 4; j++) {
                    s2[i][j] = f2_fma(qq0[i], f2_add(kk0[j], rr0[j - i + 3]), s2[i][j]);
                    s2[i][j] = f2_fma(qq1[i], f2_add(kk1[j], rr1[j - i + 3]), s2[i][j]);
                }
        }

        // fold pairs + BD rank-1 + scale + mask
        float s[4][4];
        const bool last = (jt == ntile - 1);
#pragma unroll
        for (int i = 0; i < 4; i++)
#pragma unroll
            for (int j = 0; j < 4; j++) {
                float lo, hi;
                f2_unpack(s2[i][j], lo, hi);
                float v = (lo + hi + BDc[dbase + j - i]) * 0.125f;
                if (last && (tx * 4 + j > ty * 4 + i)) v = -1e30f;
                s[i][j] = v;
            }

        // online softmax; rows on the 16 tx lanes
        float tm[4];
#pragma unroll
        for (int i = 0; i < 4; i++)
            tm[i] = fmaxf(fmaxf(s[i][0], s[i][1]), fmaxf(s[i][2], s[i][3]));
#pragma unroll
        for (int o = 1; o < 16; o <<= 1)
#pragma unroll
            for (int i = 0; i < 4; i++)
                tm[i] = fmaxf(tm[i], __shfl_xor_sync(0xffffffffu, tm[i], o));

        float corr[4], tl[4];
#pragma unroll
        for (int i = 0; i < 4; i++) {
            const float nm = fmaxf(m[i], tm[i]);
            corr[i] = __expf(m[i] - nm);
            m[i] = nm;
            float pl = 0.f;
#pragma unroll
            for (int j = 0; j < 4; j++) { s[i][j] = __expf(s[i][j] - nm); pl += s[i][j]; }
            tl[i] = pl;
        }
#pragma unroll
        for (int o = 1; o < 16; o <<= 1)
#pragma unroll
            for (int i = 0; i < 4; i++)
                tl[i] += __shfl_xor_sync(0xffffffffu, tl[i], o);
#pragma unroll
        for (int i = 0; i < 4; i++) {
            l[i] = l[i] * corr[i] + tl[i];
            const ull c2 = f2_splat(corr[i]);
            acc2[i][0] = f2_mul(acc2[i][0], c2);
            acc2[i][1] = f2_mul(acc2[i][1], c2);
            *(float4*)(Ps + (size_t)(ty * 4 + i) * PS_S + tx * 4) =
                make_float4(s[i][0], s[i][1], s[i][2], s[i][3]);
        }
        __syncthreads();   // P visible

        // ---- PV: acc2[i][p] += P[row][j] * V[j][tx*4 + 2p..] ----
#pragma unroll 1
        for (int j4 = 0; j4 < 64; j4 += 4) {
            float p0[4], p1[4], p2r[4], p3[4];
            *(float4*)p0  = *(const float4*)(Ps + (size_t)(ty * 4 + 0) * PS_S + j4);
            *(float4*)p1  = *(const float4*)(Ps + (size_t)(ty * 4 + 1) * PS_S + j4);
            *(float4*)p2r = *(const float4*)(Ps + (size_t)(ty * 4 + 2) * PS_S + j4);
            *(float4*)p3  = *(const float4*)(Ps + (size_t)(ty * 4 + 3) * PS_S + j4);
            const uint32_t vbase = Vsu + (uint32_t)j4 * 256 +
                                   (uint32_t)(((tx ^ (j4 >> 2)) & 15) << 4);
#pragma unroll
            for (int jj = 0; jj < 4; jj++) {
                ull v0, v1;
                lds_v2(v0, v1, vbase + (uint32_t)jj * 256);
                ull a0 = f2_splat(p0[jj]);
                ull a1 = f2_splat(p1[jj]);
                ull a2 = f2_splat(p2r[jj]);
                ull a3 = f2_splat(p3[jj]);
                acc2[0][0] = f2_fma(a0, v0, acc2[0][0]);
                acc2[0][1] = f2_fma(a0, v1, acc2[0][1]);
                acc2[1][0] = f2_fma(a1, v0, acc2[1][0]);
                acc2[1][1] = f2_fma(a1, v1, acc2[1][1]);
                acc2[2][0] = f2_fma(a2, v0, acc2[2][0]);
                acc2[2][1] = f2_fma(a2, v1, acc2[2][1]);
                acc2[3][0] = f2_fma(a3, v0, acc2[3][0]);
                acc2[3][1] = f2_fma(a3, v1, acc2[3][1]);
            }
        }
    }

    // epilogue: normalize, split to bf16 hi/lo (feeds MODE_O GEMM)
#pragma unroll
    for (int i = 0; i < 4; i++) {
        const float inv = 1.f / l[i];
        float v[4];
        f2_unpack(acc2[i][0], v[0], v[1]);
        f2_unpack(acc2[i][1], v[2], v[3]);
#pragma unroll
        for (int j = 0; j < 4; j++) v[j] *= inv;
        const size_t base = ((size_t)(i0 + ty * 4 + i) * BSZ + b) * DM + n * DH + tx * 4;
        __nv_bfloat16 hh[4], ll[4];
#pragma unroll
        for (int j = 0; j < 4; j++) {
            hh[j] = __float2bfloat16(v[j]);
            ll[j] = __float2bfloat16(v[j] - __bfloat162float(hh[j]));
        }
        *(__nv_bfloat162*)(g_avH + base)     = __halves2bfloat162(hh[0], hh[1]);
        *(__nv_bfloat162*)(g_avH + base + 2) = __halves2bfloat162(hh[2], hh[3]);
        *(__nv_bfloat162*)(g_avL + base)     = __halves2bfloat162(ll[0], ll[1]);
        *(__nv_bfloat162*)(g_avL + base + 2) = __halves2bfloat162(ll[2], ll[3]);
    }
}

// ---------------- LayerNorm over last dim (1024) ----------------
__global__ __launch_bounds__(256)
void ln_kernel(const float* __restrict__ gam, const float* __restrict__ bet,
               float* __restrict__ out)
{
    __shared__ float rs[8], rq[8];
    const int row = blockIdx.x;
    const int t = threadIdx.x;
    const float4 v = ((const float4*)(g_Y + (size_t)row * DM))[t];
    float s = v.x + v.y + v.z + v.w;
    float q = v.x * v.x + v.y * v.y + v.z * v.z + v.w * v.w;
#pragma unroll
    for (int o = 16; o; o >>= 1) {
        s += __shfl_down_sync(0xffffffffu, s, o);
        q += __shfl_down_sync(0xffffffffu, q, o);
    }
    if ((t & 31) == 0) { rs[t >> 5] = s; rq[t >> 5] = q; }
    __syncthreads();
    if (t == 0) {
        float ss = 0.f, qq = 0.f;
#pragma unroll
        for (int i = 0; i < 8; i++) { ss += rs[i]; qq += rq[i]; }
        rs[0] = ss; rq[0] = qq;
    }
    __syncthreads();
    const float mu   = rs[0] * (1.f / 1024.f);
    const float var  = rq[0] * (1.f / 1024.f) - mu * mu;
    const float rstd = rsqrtf(var + 1e-5f);
    const float4 g4 = ((const float4*)gam)[t];
    const float4 b4 = ((const float4*)bet)[t];
    float4 o4;
    o4.x = (v.x - mu) * rstd * g4.x + b4.x;
    o4.y = (v.y - mu) * rstd * g4.y + b4.y;
    o4.z = (v.z - mu) * rstd * g4.z + b4.z;
    o4.w = (v.w - mu) * rstd * g4.w + b4.w;
    ((float4*)(out + (size_t)row * DM))[t] = o4;
}

// ---------------- launch ----------------
extern "C" void kernel_launch(void* const* d_in, const int* in_sizes, int n_in,
                              void* d_out, int out_size)
{
    const float* w    = (const float*)d_in[0];
    const float* r    = (const float*)d_in[1];
    const float* rwb  = (const float*)d_in[2];
    const float* rrb  = (const float*)d_in[3];
    const float* mems = (const float*)d_in[4];
    const float* Wq   = (const float*)d_in[5];
    const float* bq   = (const float*)d_in[6];
    const float* Wk   = (const float*)d_in[7];
    const float* bk   = (const float*)d_in[8];
    const float* Wv   = (const float*)d_in[9];
    const float* bv   = (const float*)d_in[10];
    const float* Wr   = (const float*)d_in[11];
    const float* br   = (const float*)d_in[12];
    const float* Wo   = (const float*)d_in[13];
    const float* bo   = (const float*)d_in[14];
    const float* lng  = (const float*)d_in[15];
    const float* lnb  = (const float*)d_in[16];
    float* out = (float*)d_out;

    cudaFuncSetAttribute(attn_kernel, cudaFuncAttributeMaxDynamicSharedMemorySize,
                         ATTN_SMEM_BYTES);
    cudaFuncSetAttribute(tgemm_qkvr, cudaFuncAttributeMaxDynamicSharedMemorySize,
                         GEMM_SMEM_BYTES);
    cudaFuncSetAttribute(tgemm_o, cudaFuncAttributeMaxDynamicSharedMemorySize,
                         GEMM_SMEM_BYTES);

    const dim3 blk(256);
    // 1: splits; 2: weight transpose+splits; 3: pooled Q/K/V/R projections
    prep_splits<<<10240, blk>>>(mems, w, r);
    prep_wsplits<<<5120, blk>>>(Wq, Wk, Wv, Wr, Wo);
    tgemm_qkvr<<<dim3(8, 176), blk, GEMM_SMEM_BYTES>>>(bq, bk, bv, br);
    // 4: attention (profiled slot)
    attn_kernel<<<dim3(16, 64), blk, ATTN_SMEM_BYTES>>>(rwb, rrb);
    // 5: output projection (+residual); 6: LayerNorm
    tgemm_o<<<dim3(8, 32), blk, GEMM_SMEM_BYTES>>>(bo, w);
    ln_kernel<<<QLEN * BSZ, 256>>>(lng, lnb, out);
}

// round 16
// speedup vs baseline: 1.0349x; 1.0349x over previous
#include <cuda_runtime.h>
#include <cuda_bf16.h>
#include <cstdint>
#include <cstddef>

#define QLEN 1024
#define MLEN 1024
#define KLEN 2048
#define BSZ  4
#define DM   1024
#define NH   16
#define DH   64

typedef unsigned long long ull;

// ---------------- scratch (device globals; allocation is forbidden) ----------------
__device__ float g_Q [(size_t)BSZ * NH * QLEN * DH];   // [b][n][i][d]
__device__ float g_K [(size_t)BSZ * NH * KLEN * DH];   // [b][n][j][d]
__device__ float g_RK[(size_t)NH * KLEN * DH];         // [n][jr][d]
__device__ float g_Y [(size_t)QLEN * BSZ * DM];        // w + attn_out (pre-LN)

// bf16 split operands
__device__ __nv_bfloat16 g_catH[(size_t)2 * QLEN * BSZ * DM];  // [mems;w] rows
__device__ __nv_bfloat16 g_catL[(size_t)2 * QLEN * BSZ * DM];
__device__ __nv_bfloat16 g_rH  [(size_t)KLEN * DM];
__device__ __nv_bfloat16 g_rL  [(size_t)KLEN * DM];
__device__ __nv_bfloat16 g_avH [(size_t)QLEN * BSZ * DM];      // attn out hi
__device__ __nv_bfloat16 g_avL [(size_t)QLEN * BSZ * DM];      // attn out lo
__device__ __nv_bfloat16 g_WtH [5][(size_t)DM * DM];   // transposed weights [n][k]
__device__ __nv_bfloat16 g_WtL [5][(size_t)DM * DM];
// V stored transposed + bf16-split: [b][n][d][j]
__device__ __nv_bfloat16 g_vTH [(size_t)BSZ * NH * DH * KLEN];
__device__ __nv_bfloat16 g_vTL [(size_t)BSZ * NH * DH * KLEN];

#define MODE_Q 0
#define MODE_K 1
#define MODE_V 2
#define MODE_R 3
#define MODE_O 4

// ---------------- PTX helpers ----------------
__device__ __forceinline__ uint32_t smem_u32(const void* p) {
    uint32_t a;
    asm("{ .reg .u64 t; cvta.to.shared.u64 t, %1; cvt.u32.u64 %0, t; }"
        : "=r"(a) : "l"(p));
    return a;
}
__device__ __forceinline__ void ldsm_x4(uint32_t* r, uint32_t addr) {
    asm volatile("ldmatrix.sync.aligned.m8n8.x4.shared.b16 {%0,%1,%2,%3}, [%4];"
                 : "=r"(r[0]), "=r"(r[1]), "=r"(r[2]), "=r"(r[3]) : "r"(addr));
}
__device__ __forceinline__ void mma16816(float* c, const uint32_t* a,
                                         uint32_t b0, uint32_t b1) {
    asm volatile(
        "mma.sync.aligned.m16n8k16.row.col.f32.bf16.bf16.f32 "
        "{%0,%1,%2,%3}, {%4,%5,%6,%7}, {%8,%9}, {%0,%1,%2,%3};"
        : "+f"(c[0]), "+f"(c[1]), "+f"(c[2]), "+f"(c[3])
        : "r"(a[0]), "r"(a[1]), "r"(a[2]), "r"(a[3]), "r"(b0), "r"(b1));
}
// f32x2 packed math (sm_100+ base feature)
__device__ __forceinline__ ull f2_add(ull a, ull b) {
    ull c; asm("add.rn.f32x2 %0, %1, %2;" : "=l"(c) : "l"(a), "l"(b)); return c;
}
__device__ __forceinline__ ull f2_fma(ull a, ull b, ull c) {
    ull d; asm("fma.rn.f32x2 %0, %1, %2, %3;" : "=l"(d) : "l"(a), "l"(b), "l"(c)); return d;
}
__device__ __forceinline__ void f2_unpack(ull v, float& lo, float& hi) {
    asm("mov.b64 {%0, %1}, %2;" : "=f"(lo), "=f"(hi) : "l"(v));
}
__device__ __forceinline__ void lds_v2(ull& x, ull& y, uint32_t a) {
    asm volatile("ld.shared.v2.u64 {%0, %1}, [%2];" : "=l"(x), "=l"(y) : "r"(a));
}

// ---------------- fused prep: splits ----------------
__device__ __forceinline__ void split_one(const float* __restrict__ in,
                                          __nv_bfloat16* __restrict__ hi,
                                          __nv_bfloat16* __restrict__ lo, int i)
{
    float4 v = ((const float4*)in)[i];
    __nv_bfloat16 h0 = __float2bfloat16(v.x), h1 = __float2bfloat16(v.y);
    __nv_bfloat16 h2 = __float2bfloat16(v.z), h3 = __float2bfloat16(v.w);
    __nv_bfloat16 l0 = __float2bfloat16(v.x - __bfloat162float(h0));
    __nv_bfloat16 l1 = __float2bfloat16(v.y - __bfloat162float(h1));
    __nv_bfloat16 l2 = __float2bfloat16(v.z - __bfloat162float(h2));
    __nv_bfloat16 l3 = __float2bfloat16(v.w - __bfloat162float(h3));
    ((__nv_bfloat162*)hi)[2 * i]     = __halves2bfloat162(h0, h1);
    ((__nv_bfloat162*)hi)[2 * i + 1] = __halves2bfloat162(h2, h3);
    ((__nv_bfloat162*)lo)[2 * i]     = __halves2bfloat162(l0, l1);
    ((__nv_bfloat162*)lo)[2 * i + 1] = __halves2bfloat162(l2, l3);
}

__global__ __launch_bounds__(256)
void prep_splits(const float* __restrict__ mems, const float* __restrict__ w,
                 const float* __restrict__ r)
{
    const int bx = blockIdx.x, t = threadIdx.x;
    if (bx < 4096) {
        split_one(mems, g_catH, g_catL, bx * 256 + t);
    } else if (bx < 8192) {
        split_one(w, g_catH + (size_t)4096 * DM, g_catL + (size_t)4096 * DM,
                  (bx - 4096) * 256 + t);
    } else {
        split_one(r, g_rH, g_rL, (bx - 8192) * 256 + t);
    }
}

__global__ __launch_bounds__(256)
void prep_wsplits(const float* __restrict__ Wq, const float* __restrict__ Wk,
                  const float* __restrict__ Wv, const float* __restrict__ Wr,
                  const float* __restrict__ Wo)
{
    __shared__ float tile[32][33];
    const int widx = blockIdx.x >> 10;
    const int loc  = blockIdx.x & 1023;
    const int n0 = (loc & 31) * 32, k0 = (loc >> 5) * 32;
    const int tx = threadIdx.x & 31, ty = threadIdx.x >> 5;
    const float* W = (widx == 0) ? Wq : (widx == 1) ? Wk
                   : (widx == 2) ? Wv : (widx == 3) ? Wr : Wo;
    __nv_bfloat16* hi = g_WtH[widx];
    __nv_bfloat16* lo = g_WtL[widx];
    for (int rr = ty; rr < 32; rr += 8)
        tile[rr][tx] = W[(size_t)(k0 + rr) * DM + n0 + tx];
    __syncthreads();
    for (int rr = ty; rr < 32; rr += 8) {
        float v = tile[tx][rr];
        __nv_bfloat16 h = __float2bfloat16(v);
        __nv_bfloat16 l = __float2bfloat16(v - __bfloat162float(h));
        hi[(size_t)(n0 + rr) * DM + k0 + tx] = h;
        lo[(size_t)(n0 + rr) * DM + k0 + tx] = l;
    }
}

// ---------------- mma.sync split-bf16 GEMM body ----------------
#define KSC  64
#define STR  72
#define MAT_BF (128 * STR)
#define GEMM_SMEM_BYTES (4 * MAT_BF * 2)

__device__ __forceinline__ void tgemm_body(
    int mode, int m0, int n0,
    const __nv_bfloat16* __restrict__ AH, const __nv_bfloat16* __restrict__ AL,
    const __nv_bfloat16* __restrict__ BH, const __nv_bfloat16* __restrict__ BL,
    const float* __restrict__ bias, const float* __restrict__ addend,
    __nv_bfloat16* smb)
{
    __nv_bfloat16* sAH = smb;
    __nv_bfloat16* sAL = smb + MAT_BF;
    __nv_bfloat16* sBH = smb + 2 * MAT_BF;
    __nv_bfloat16* sBL = smb + 3 * MAT_BF;

    const int t    = threadIdx.x;
    const int wid  = t >> 5;
    const int lane = t & 31;
    const int wm   = wid >> 2;
    const int wn   = wid & 3;

    const uint32_t sAHu = smem_u32(sAH), sALu = smem_u32(sAL);
    const uint32_t sBHu = smem_u32(sBH), sBLu = smem_u32(sBL);

    const int aoff  = (lane & 15) * STR + ((lane >> 4) << 3);
    const int b4off = lane * STR;

    float acc[4][4][4];
#pragma unroll
    for (int i = 0; i < 4; i++)
#pragma unroll
        for (int j = 0; j < 4; j++)
#pragma unroll
            for (int k = 0; k < 4; k++) acc[i][j][k] = 0.f;

    for (int c = 0; c < 16; c++) {
        __syncthreads();
        const size_t coff = (size_t)c * KSC;
#pragma unroll
        for (int i = 0; i < 4; i++) {
            const int idx = t + i * 256;
            const int row = idx >> 3, g = (idx & 7) * 8;
            *(uint4*)(sAH + row * STR + g) = *(const uint4*)(AH + (size_t)(m0 + row) * DM + coff + g);
            *(uint4*)(sAL + row * STR + g) = *(const uint4*)(AL + (size_t)(m0 + row) * DM + coff + g);
            *(uint4*)(sBH + row * STR + g) = *(const uint4*)(BH + (size_t)(n0 + row) * DM + coff + g);
            *(uint4*)(sBL + row * STR + g) = *(const uint4*)(BL + (size_t)(n0 + row) * DM + coff + g);
        }
        __syncthreads();

#pragma unroll
        for (int ks = 0; ks < KSC; ks += 16) {
            uint32_t bh0[4], bh8[4], bl0[4], bl8[4];
            const uint32_t bbase = (uint32_t)((wn * 32) * STR + ks + b4off) * 2;
            ldsm_x4(bh0, sBHu + bbase);
            ldsm_x4(bh8, sBHu + bbase + 16);
            ldsm_x4(bl0, sBLu + bbase);
            ldsm_x4(bl8, sBLu + bbase + 16);
#pragma unroll
            for (int mt = 0; mt < 4; mt++) {
                const int mrow = wm * 64 + mt * 16;
                uint32_t ah[4], al[4];
                ldsm_x4(ah, sAHu + (uint32_t)(mrow * STR + ks + aoff) * 2);
                ldsm_x4(al, sALu + (uint32_t)(mrow * STR + ks + aoff) * 2);
#pragma unroll
                for (int nt = 0; nt < 4; nt++) {
                    mma16816(acc[mt][nt], ah, bh0[nt], bh8[nt]);
                    mma16816(acc[mt][nt], ah, bl0[nt], bl8[nt]);
                    mma16816(acc[mt][nt], al, bh0[nt], bh8[nt]);
                }
            }
        }
    }

    const int g  = lane >> 2;
    const int cp = (lane & 3) * 2;
#pragma unroll
    for (int mt = 0; mt < 4; mt++) {
        const int rbase = m0 + wm * 64 + mt * 16;
#pragma unroll
        for (int nt = 0; nt < 4; nt++) {
            const int col = n0 + wn * 32 + nt * 8 + cp;
            const float b0 = bias[col], b1 = bias[col + 1];
            const int nn = col >> 6, d = col & 63;
#pragma unroll
            for (int hrow = 0; hrow < 2; hrow++) {
                const int row = rbase + g + hrow * 8;
                float v0 = acc[mt][nt][hrow * 2 + 0] + b0;
                float v1 = acc[mt][nt][hrow * 2 + 1] + b1;
                if (mode == MODE_O) {
                    const float2 ad = *(const float2*)(addend + (size_t)row * DM + col);
                    *(float2*)(g_Y + (size_t)row * DM + col) =
                        make_float2(v0 + ad.x, v1 + ad.y);
                } else if (mode == MODE_R) {
                    *(float2*)(g_RK + ((size_t)nn * KLEN + row) * DH + d) =
                        make_float2(v0, v1);
                } else if (mode == MODE_Q) {
                    const int ip = row >> 2, bb = row & 3;
                    *(float2*)(g_Q + (((size_t)bb * NH + nn) * QLEN + ip) * DH + d) =
                        make_float2(v0, v1);
                } else if (mode == MODE_K) {
                    const int ip = row >> 2, bb = row & 3;
                    *(float2*)(g_K + (((size_t)bb * NH + nn) * KLEN + ip) * DH + d) =
                        make_float2(v0, v1);
                } else {   // MODE_V: transposed bf16-split store [b][n][d][j]
                    const int ip = row >> 2, bb = row & 3;
                    __nv_bfloat16 h0 = __float2bfloat16(v0);
                    __nv_bfloat16 l0b = __float2bfloat16(v0 - __bfloat162float(h0));
                    __nv_bfloat16 h1 = __float2bfloat16(v1);
                    __nv_bfloat16 l1b = __float2bfloat16(v1 - __bfloat162float(h1));
                    const size_t vb = (((size_t)bb * NH + nn) * DH + d) * KLEN + ip;
                    g_vTH[vb] = h0;        g_vTL[vb] = l0b;
                    g_vTH[vb + KLEN] = h1; g_vTL[vb + KLEN] = l1b;
                }
            }
        }
    }
}

__global__ __launch_bounds__(256, 2)
void tgemm_qkvr(const float* __restrict__ bq, const float* __restrict__ bk,
                const float* __restrict__ bv, const float* __restrict__ br)
{
    extern __shared__ __align__(16) __nv_bfloat16 smb[];
    const int my = blockIdx.y;
    int mode, mt;
    const __nv_bfloat16 *AH, *AL;
    const float* bias;
    if (my < 32)        { mode = MODE_Q; mt = my;       AH = g_catH + (size_t)4096 * DM; AL = g_catL + (size_t)4096 * DM; bias = bq; }
    else if (my < 96)   { mode = MODE_K; mt = my - 32;  AH = g_catH; AL = g_catL; bias = bk; }
    else if (my < 160)  { mode = MODE_V; mt = my - 96;  AH = g_catH; AL = g_catL; bias = bv; }
    else                { mode = MODE_R; mt = my - 160; AH = g_rH;   AL = g_rL;   bias = br; }
    tgemm_body(mode, mt * 128, blockIdx.x * 128,
               AH, AL, g_WtH[mode], g_WtL[mode], bias, nullptr, smb);
}

__global__ __launch_bounds__(256, 2)
void tgemm_o(const float* __restrict__ bo, const float* __restrict__ w)
{
    extern __shared__ __align__(16) __nv_bfloat16 smb[];
    tgemm_body(MODE_O, blockIdx.y * 128, blockIdx.x * 128,
               g_avH, g_avL, g_WtH[4], g_WtL[4], bo, w, smb);
}

// ---------------- flash attention: f32x2 score + mma.sync PV ----------------
#define AB_QS   0
#define AB_KS   16384
#define AB_RS   32768
#define AB_VTH  65536
#define AB_VTL  74752
#define AB_PH   83968
#define AB_PL   93184
#define AB_DB   102400
#define AB_BDC  102656
#define AB_CORR 103168
#define AB_L    103424
#define ATTN_SMEM_BYTES 103680

__device__ __forceinline__ int swf(int row, int g) {
    return row * 64 + (((g ^ (row >> 2)) & 15) << 2);
}

__global__ __launch_bounds__(256, 2)
void attn_kernel(const float* __restrict__ rwb, const float* __restrict__ rrb)
{
    extern __shared__ float sm[];
    char* smc = (char*)sm;
    float* db    = (float*)(smc + AB_DB);
    float* BDc   = (float*)(smc + AB_BDC);
    float* corrS = (float*)(smc + AB_CORR);
    float* lS    = (float*)(smc + AB_L);
    const uint32_t smu = smem_u32(sm);
    const uint32_t qSu = smu + AB_QS;
    const uint32_t Ksu = smu + AB_KS;
    const uint32_t Rsu = smu + AB_RS;

    const int t    = threadIdx.x;
    const int wid  = t >> 5;
    const int lane = t & 31;
    const int qt = 15 - (int)blockIdx.x;
    const int i0 = qt * 64;
    const int h  = blockIdx.y;
    const int b  = h >> 4;
    const int n  = h & 15;
    const int tx = t & 15;
    const int ty = t >> 4;

    const float* Qh = g_Q  + ((size_t)b * NH + n) * QLEN * DH;
    const float* Kh = g_K  + ((size_t)b * NH + n) * KLEN * DH;
    const float* Rh = g_RK + (size_t)n * KLEN * DH;
    const __nv_bfloat16* vTH = g_vTH + ((size_t)b * NH + n) * DH * KLEN;
    const __nv_bfloat16* vTL = g_vTL + ((size_t)b * NH + n) * DH * KLEN;

    if (t < 64) db[t] = rrb[n * DH + t] - rwb[n * DH + t];
    for (int e = t; e < 64 * 16; e += 256) {
        const int r = e >> 4, g = e & 15;
        float4 q4 = *(const float4*)(Qh + (size_t)(i0 + r) * DH + g * 4);
        float4 w4 = *(const float4*)(rwb + n * DH + g * 4);
        q4.x += w4.x; q4.y += w4.y; q4.z += w4.z; q4.w += w4.w;
        *(float4*)(smc + AB_QS + swf(r, g) * 4) = q4;
    }

    const int dbase = tx * 4 - ty * 4 + 63;
    uint32_t aq[4], ak[4], ar[7];
    int kr[7];
#pragma unroll
    for (int i = 0; i < 4; i++) aq[i] = qSu + (uint32_t)(ty * 4 + i) * 256;
#pragma unroll
    for (int j = 0; j < 4; j++) ak[j] = Ksu + (uint32_t)(tx * 4 + j) * 256;
#pragma unroll
    for (int o = 0; o < 7; o++) {
        const int ridx = dbase - 3 + o;
        ar[o] = Rsu + (uint32_t)ridx * 256;
        kr[o] = (ridx >> 2) & 15;
    }

    float m[4], l[4];
    float C[4][4];   // persistent PV accumulator (mma C fragments, m16 x n32 per warp)
#pragma unroll
    for (int i = 0; i < 4; i++) {
        m[i] = -1e30f; l[i] = 0.f;
#pragma unroll
        for (int j = 0; j < 4; j++) C[i][j] = 0.f;
    }
    const int mb = (wid >> 1) * 16;
    const int nb = (wid & 1) * 32;

    const int ntile = qt + 17;
    for (int jt = 0; jt < ntile; jt++) {
        const int j0 = jt * 64;
        __syncthreads();

        for (int e = t; e < 64 * 16; e += 256) {
            const int c = e >> 4, g = e & 15;
            *(float4*)(smc + AB_KS + swf(c, g) * 4) =
                *(const float4*)(Kh + (size_t)(j0 + c) * DH + g * 4);
        }
        for (int e = t; e < 1024; e += 256) {
            const int mat = e >> 9, idx = e & 511;
            const int drow = idx >> 3, g = idx & 7;
            const __nv_bfloat16* src = (mat == 0) ? vTH : vTL;
            const int dst = (mat == 0) ? AB_VTH : AB_VTL;
            *(uint4*)(smc + dst + drow * 144 + g * 16) =
                *(const uint4*)(src + (size_t)drow * KLEN + j0 + g * 8);
        }
        const int rb = j0 - i0 + (QLEN - 64);
        for (int e = t; e < 128 * 16; e += 256) {
            const int ri = e & 127, g = e >> 7;
            const int jr = rb + ri;
            float4 r4 = make_float4(0.f, 0.f, 0.f, 0.f);
            if (jr < KLEN) r4 = *(const float4*)(Rh + (size_t)jr * DH + g * 4);
            *(float4*)(smc + AB_RS + swf(ri, g) * 4) = r4;
        }
        __syncthreads();

        if (t < 128) {
            float sum = 0.f;
#pragma unroll
            for (int g = 0; g < 16; g++) {
                float4 rv = *(const float4*)(smc + AB_RS + swf(t, g) * 4);
                float4 dv = *(const float4*)(db + g * 4);
                sum = fmaf(rv.x, dv.x, sum); sum = fmaf(rv.y, dv.y, sum);
                sum = fmaf(rv.z, dv.z, sum); sum = fmaf(rv.w, dv.w, sum);
            }
            BDc[t] = sum;
        }
        __syncthreads();

        ull s2[4][4];
#pragma unroll
        for (int i = 0; i < 4; i++)
#pragma unroll
            for (int j = 0; j < 4; j++) s2[i][j] = 0ull;

#pragma unroll 1
        for (int g = 0; g < 16; g++) {
            ull qq0[4], qq1[4], kk0[4], kk1[4], rr0[7], rr1[7];
            const uint32_t oq = (uint32_t)((g ^ ty) << 4);
            const uint32_t ok = (uint32_t)((g ^ tx) << 4);
#pragma unroll
            for (int i = 0; i < 4; i++) lds_v2(qq0[i], qq1[i], aq[i] + oq);
#pragma unroll
            for (int j = 0; j < 4; j++) lds_v2(kk0[j], kk1[j], ak[j] + ok);
#pragma unroll
            for (int o = 0; o < 7; o++)
                lds_v2(rr0[o], rr1[o], ar[o] + (uint32_t)((g ^ kr[o]) << 4));
#pragma unroll
            for (int i = 0; i < 4; i++)
#pragma unroll
                for (int j = 0; j < 4; j++) {
                    s2[i][j] = f2_fma(qq0[i], f2_add(kk0[j], rr0[j - i + 3]), s2[i][j]);
                    s2[i][j] = f2_fma(qq1[i], f2_add(kk1[j], rr1[j - i + 3]), s2[i][j]);
                }
        }

        float s[4][4];
        const bool last = (jt == ntile - 1);
#pragma unroll
        for (int i = 0; i < 4; i++)
#pragma unroll
            for (int j = 0; j < 4; j++) {
                float lo, hi;
                f2_unpack(s2[i][j], lo, hi);
                float v = (lo + hi + BDc[dbase + j - i]) * 0.125f;
                if (last && (tx * 4 + j > ty * 4 + i)) v = -1e30f;
                s[i][j] = v;
            }

        float tm[4];
#pragma unroll
        for (int i = 0; i < 4; i++)
            tm[i] = fmaxf(fmaxf(s[i][0], s[i][1]), fmaxf(s[i][2], s[i][3]));
#pragma unroll
        for (int o = 1; o < 16; o <<= 1)
#pragma unroll
            for (int i = 0; i < 4; i++)
                tm[i] = fmaxf(tm[i], __shfl_xor_sync(0xffffffffu, tm[i], o));

        float corr[4], tl[4];
#pragma unroll
        for (int i = 0; i < 4; i++) {
            const float nm = fmaxf(m[i], tm[i]);
            corr[i] = __expf(m[i] - nm);
            m[i] = nm;
            float pl = 0.f;
#pragma unroll
            for (int j = 0; j < 4; j++) { s[i][j] = __expf(s[i][j] - nm); pl += s[i][j]; }
            tl[i] = pl;
        }
#pragma unroll
        for (int o = 1; o < 16; o <<= 1)
#pragma unroll
            for (int i = 0; i < 4; i++)
                tl[i] += __shfl_xor_sync(0xffffffffu, tl[i], o);

#pragma unroll
        for (int i = 0; i < 4; i++) {
            l[i] = l[i] * corr[i] + tl[i];
            const int row = ty * 4 + i;
            if (tx == 0) corrS[row] = corr[i];
            __nv_bfloat16 ph[4], pl4[4];
#pragma unroll
            for (int j = 0; j < 4; j++) {
                ph[j]  = __float2bfloat16(s[i][j]);
                pl4[j] = __float2bfloat16(s[i][j] - __bfloat162float(ph[j]));
            }
            *(__nv_bfloat162*)(smc + AB_PH + row * 144 + tx * 8)     = __halves2bfloat162(ph[0], ph[1]);
            *(__nv_bfloat162*)(smc + AB_PH + row * 144 + tx * 8 + 4) = __halves2bfloat162(ph[2], ph[3]);
            *(__nv_bfloat162*)(smc + AB_PL + row * 144 + tx * 8)     = __halves2bfloat162(pl4[0], pl4[1]);
            *(__nv_bfloat162*)(smc + AB_PL + row * 144 + tx * 8 + 4) = __halves2bfloat162(pl4[2], pl4[3]);
        }
        __syncthreads();

        const float c0 = corrS[mb + (lane >> 2)];
        const float c1 = corrS[mb + (lane >> 2) + 8];
#pragma unroll
        for (int nt = 0; nt < 4; nt++) {
            C[nt][0] *= c0; C[nt][1] *= c0; C[nt][2] *= c1; C[nt][3] *= c1;
        }
        const uint32_t pA  = smu + AB_PH + (uint32_t)(mb + (lane & 15)) * 144 + ((lane >> 4) << 4);
        const uint32_t pAl = pA + (AB_PL - AB_PH);
        const uint32_t pB  = smu + AB_VTH + (uint32_t)(nb + lane) * 144;
        const uint32_t pBl = pB + (AB_VTL - AB_VTH);
#pragma unroll
        for (int k0 = 0; k0 < 64; k0 += 16) {
            uint32_t ah[4], al[4], bh0[4], bh8[4], bl0[4], bl8[4];
            ldsm_x4(ah,  pA  + k0 * 2);
            ldsm_x4(al,  pAl + k0 * 2);
            ldsm_x4(bh0, pB  + k0 * 2);
            ldsm_x4(bh8, pB  + k0 * 2 + 16);
            ldsm_x4(bl0, pBl + k0 * 2);
            ldsm_x4(bl8, pBl + k0 * 2 + 16);
#pragma unroll
            for (int nt = 0; nt < 4; nt++) {
                mma16816(C[nt], ah, bh0[nt], bh8[nt]);
                mma16816(C[nt], al, bh0[nt], bh8[nt]);
                mma16816(C[nt], ah, bl0[nt], bl8[nt]);
            }
        }
    }

#pragma unroll
    for (int i = 0; i < 4; i++)
        if (tx == 0) lS[ty * 4 + i] = l[i];
    __syncthreads();
    const float inv0 = 1.f / lS[mb + (lane >> 2)];
    const float inv1 = 1.f / lS[mb + (lane >> 2) + 8];
    const int r0 = i0 + mb + (lane >> 2);
#pragma unroll
    for (int nt = 0; nt < 4; nt++) {
        const int d = nb + nt * 8 + (lane & 3) * 2;
#pragma unroll
        for (int hrow = 0; hrow < 2; hrow++) {
            const int row = r0 + hrow * 8;
            const float inv = hrow ? inv1 : inv0;
            const float v0 = C[nt][hrow * 2 + 0] * inv;
            const float v1 = C[nt][hrow * 2 + 1] * inv;
            const size_t base = ((size_t)row * BSZ + b) * DM + n * DH + d;
            __nv_bfloat16 h0 = __float2bfloat16(v0);
            __nv_bfloat16 l0b = __float2bfloat16(v0 - __bfloat162float(h0));
            __nv_bfloat16 h1 = __float2bfloat16(v1);
            __nv_bfloat16 l1b = __float2bfloat16(v1 - __bfloat162float(h1));
            *(__nv_bfloat162*)(g_avH + base) = __halves2bfloat162(h0, h1);
            *(__nv_bfloat162*)(g_avL + base) = __halves2bfloat162(l0b, l1b);
        }
    }
}

// ---------------- LayerNorm over last dim (1024) ----------------
__global__ __launch_bounds__(256)
void ln_kernel(const float* __restrict__ gam, const float* __restrict__ bet,
               float* __restrict__ out)
{
    __shared__ float rs[8], rq[8];
    const int row = blockIdx.x;
    const int t = threadIdx.x;
    const float4 v = ((const float4*)(g_Y + (size_t)row * DM))[t];
    float s = v.x + v.y + v.z + v.w;
    float q = v.x * v.x + v.y * v.y + v.z * v.z + v.w * v.w;
#pragma unroll
    for (int o = 16; o; o >>= 1) {
        s += __shfl_down_sync(0xffffffffu, s, o);
        q += __shfl_down_sync(0xffffffffu, q, o);
    }
    if ((t & 31) == 0) { rs[t >> 5] = s; rq[t >> 5] = q; }
    __syncthreads();
    if (t == 0) {
        float ss = 0.f, qq = 0.f;
#pragma unroll
        for (int i = 0; i < 8; i++) { ss += rs[i]; qq += rq[i]; }
        rs[0] = ss; rq[0] = qq;
    }
    __syncthreads();
    const float mu   = rs[0] * (1.f / 1024.f);
    const float var  = rq[0] * (1.f / 1024.f) - mu * mu;
    const float rstd = rsqrtf(var + 1e-5f);
    const float4 g4 = ((const float4*)gam)[t];
    const float4 b4 = ((const float4*)bet)[t];
    float4 o4;
    o4.x = (v.x - mu) * rstd * g4.x + b4.x;
    o4.y = (v.y - mu) * rstd * g4.y + b4.y;
    o4.z = (v.z - mu) * rstd * g4.z + b4.z;
    o4.w = (v.w - mu) * rstd * g4.w + b4.w;
    ((float4*)(out + (size_t)row * DM))[t] = o4;
}

// ---------------- launch ----------------
extern "C" void kernel_launch(void* const* d_in, const int* in_sizes, int n_in,
                              void* d_out, int out_size)
{
    const float* w    = (const float*)d_in[0];
    const float* r    = (const float*)d_in[1];
    const float* rwb  = (const float*)d_in[2];
    const float* rrb  = (const float*)d_in[3];
    const float* mems = (const float*)d_in[4];
    const float* Wq   = (const float*)d_in[5];
    const float* bq   = (const float*)d_in[6];
    const float* Wk   = (const float*)d_in[7];
    const float* bk   = (const float*)d_in[8];
    const float* Wv   = (const float*)d_in[9];
    const float* bv   = (const float*)d_in[10];
    const float* Wr   = (const float*)d_in[11];
    const float* br   = (const float*)d_in[12];
    const float* Wo   = (const float*)d_in[13];
    const float* bo   = (const float*)d_in[14];
    const float* lng  = (const float*)d_in[15];
    const float* lnb  = (const float*)d_in[16];
    float* out = (float*)d_out;

    cudaFuncSetAttribute(attn_kernel, cudaFuncAttributeMaxDynamicSharedMemorySize,
                         ATTN_SMEM_BYTES);
    cudaFuncSetAttribute(tgemm_qkvr, cudaFuncAttributeMaxDynamicSharedMemorySize,
                         GEMM_SMEM_BYTES);
    cudaFuncSetAttribute(tgemm_o, cudaFuncAttributeMaxDynamicSharedMemorySize,
                         GEMM_SMEM_BYTES);

    const dim3 blk(256);
    prep_splits<<<10240, blk>>>(mems, w, r);
    prep_wsplits<<<5120, blk>>>(Wq, Wk, Wv, Wr, Wo);
    tgemm_qkvr<<<dim3(8, 176), blk, GEMM_SMEM_BYTES>>>(bq, bk, bv, br);
    // slot 4: attention (profiled)
    attn_kernel<<<dim3(16, 64), blk, ATTN_SMEM_BYTES>>>(rwb, rrb);
    tgemm_o<<<dim3(8, 32), blk, GEMM_SMEM_BYTES>>>(bo, w);
    ln_kernel<<<QLEN * BSZ, 256>>>(lng, lnb, out);
}